// round 2
// baseline (speedup 1.0000x reference)
#include <cuda_runtime.h>

#define TOKENS   64
#define IN_F     8192
#define OUT_F    8192
#define QIN      7936
#define OUTL     256
#define KC       64
#define NO       64
#define NCHUNK   128       // IN_F / KC
#define QCHUNKS  124       // QIN / KC
#define INROW    132       // padded dup-pair row stride (floats): 2*64 + 4

// Scratch: permuted input, [k][t] layout (feature-major, 64 tokens contiguous)
__device__ float g_perm_in[IN_F * TOKENS];

// ---------------------------------------------------------------------------
// Kernel 1: scatter input columns through inv_col_perm.
// perm_in[inv[j]][t] = input[t][j]   (reads coalesced: lanes along j)
// ---------------------------------------------------------------------------
__global__ void perm_kernel(const float* __restrict__ inp,
                            const int* __restrict__ inv) {
    int j = blockIdx.x * blockDim.x + threadIdx.x;
    if (j < IN_F) {
        int dst = inv[j];
        #pragma unroll
        for (int t = 0; t < TOKENS; ++t)
            g_perm_in[dst * TOKENS + t] = inp[t * IN_F + j];
    }
}

// ---------------------------------------------------------------------------
// Packed f32x2 FMA (Blackwell)
// ---------------------------------------------------------------------------
__device__ __forceinline__ unsigned long long fma2(unsigned long long a,
                                                   unsigned long long b,
                                                   unsigned long long c) {
    unsigned long long d;
    asm("fma.rn.f32x2 %0, %1, %2, %3;" : "=l"(d) : "l"(a), "l"(b), "l"(c));
    return d;
}

// ---------------------------------------------------------------------------
// Kernel 2: main fused transform + GEMM.
// Grid: 128 CTAs (one per 64 out-features). Block: 256 threads.
// Each thread: 4 outs x 4 tokens = 16 fp32 accumulators as 8 f32x2 pairs.
// ---------------------------------------------------------------------------
__global__ void __launch_bounds__(256)
linear_kernel(const float* __restrict__ q_w,
              const float* __restrict__ fp_w,
              const float* __restrict__ alpha,
              const float* __restrict__ bias,
              const float* __restrict__ noise,
              float* __restrict__ out) {
    extern __shared__ float smem[];
    float* w_s  = smem;                       // [2][KC][NO]      (swizzled)
    float* in_s = smem + 2 * KC * NO;         // [2][KC][INROW]   (dup pairs)
    float* al_s = in_s + 2 * KC * INROW;      // [NO]

    const int tid   = threadIdx.x;
    const int go    = blockIdx.x * NO;

    // staging decomposition (identical for w tile and in tile):
    //   rbase = tid>>4 in [0,16), c4/tt = tid&15
    //   unit i handles row rbase + 16*i
    const int rbase = tid >> 4;
    const int c4    = tid & 15;
    const int swz_st = (c4 & 7) << 2;         // store-side swizzle (k>>2 == c4)

    // compute decomposition
    const int og = tid & 15;                  // 16 out-groups of 4
    const int tg = tid >> 4;                  // 16 token-groups of 4
    const int o0 = og * 4;

    if (tid < NO) al_s[tid] = alpha[go + tid];

    unsigned long long acc[2][4];
    #pragma unroll
    for (int a = 0; a < 2; ++a)
        #pragma unroll
        for (int t = 0; t < 4; ++t) acc[a][t] = 0ull;

    // ---- staging helpers (macros keep everything in registers) ----
    float4 rw[4], rn[4];
    float  ri[16];

    #define LDG_STAGE(c)                                                        \
    {                                                                           \
        const int kbase = (c) * KC;                                             \
        const bool isq = (c) < QCHUNKS;                                         \
        _Pragma("unroll")                                                       \
        for (int i = 0; i < 4; ++i) {                                           \
            int row = rbase + 16 * i;                                           \
            if (isq) {                                                          \
                long off = (long)(go + row) * QIN + kbase + c4 * 4;             \
                rw[i] = *(const float4*)(q_w + off);                            \
                rn[i] = *(const float4*)(noise + off);                          \
            } else {                                                            \
                long off = (long)(go + row) * OUTL + (kbase - QIN) + c4 * 4;    \
                rw[i] = *(const float4*)(fp_w + off);                           \
            }                                                                   \
        }                                                                       \
        _Pragma("unroll")                                                       \
        for (int i = 0; i < 4; ++i) {                                           \
            int krow = rbase + 16 * i;                                          \
            _Pragma("unroll")                                                   \
            for (int s = 0; s < 4; ++s)                                         \
                ri[i * 4 + s] = g_perm_in[(kbase + krow) * TOKENS + c4 + 16 * s];\
        }                                                                       \
    }

    #define STS_STAGE(c, b)                                                     \
    {                                                                           \
        const bool isq = (c) < QCHUNKS;                                         \
        float* wb = w_s + (b) * KC * NO;                                        \
        float* ib = in_s + (b) * KC * INROW;                                    \
        _Pragma("unroll")                                                       \
        for (int i = 0; i < 4; ++i) {                                           \
            int row = rbase + 16 * i;                                           \
            float a  = al_s[row];                                               \
            float dh = a * (0.5f / 7.0f);                                       \
            float v[4] = {rw[i].x, rw[i].y, rw[i].z, rw[i].w};                  \
            if (isq) {                                                          \
                float n[4] = {rn[i].x, rn[i].y, rn[i].z, rn[i].w};              \
                _Pragma("unroll")                                               \
                for (int j = 0; j < 4; ++j) {                                   \
                    float w = v[j];                                             \
                    v[j] = (w >= a) ? a : ((w <= -a) ? -a : fmaf(n[j], dh, w)); \
                }                                                               \
            }                                                                   \
            int oo = row ^ swz_st;                                              \
            _Pragma("unroll")                                                   \
            for (int j = 0; j < 4; ++j)                                         \
                wb[(c4 * 4 + j) * NO + oo] = v[j];                              \
        }                                                                       \
        _Pragma("unroll")                                                       \
        for (int i = 0; i < 4; ++i) {                                           \
            int krow = rbase + 16 * i;                                          \
            _Pragma("unroll")                                                   \
            for (int s = 0; s < 4; ++s) {                                       \
                float v = ri[i * 4 + s];                                        \
                *(float2*)(ib + krow * INROW + 2 * (c4 + 16 * s)) =             \
                    make_float2(v, v);                                          \
            }                                                                   \
        }                                                                       \
    }

    // ---- prologue: stage chunk 0 into buffer 0 ----
    LDG_STAGE(0);
    __syncthreads();            // al_s visible
    STS_STAGE(0, 0);
    __syncthreads();

    // ---- main loop: double-buffered ----
    for (int c = 0; c < NCHUNK; ++c) {
        const int cb = c & 1, nb = cb ^ 1;
        const bool pf = (c + 1 < NCHUNK);
        if (pf) LDG_STAGE(c + 1);           // LDGs in flight during compute

        const float* wb = w_s + cb * KC * NO;
        const float* ib = in_s + cb * KC * INROW;

        #pragma unroll 8
        for (int kk = 0; kk < KC; ++kk) {
            int sw = ((kk >> 2) & 7) << 2;
            const ulonglong2 wv = *(const ulonglong2*)(wb + kk * NO + (o0 ^ sw));
            const ulonglong2 pA = *(const ulonglong2*)(ib + kk * INROW + 8 * tg);
            const ulonglong2 pB = *(const ulonglong2*)(ib + kk * INROW + 8 * tg + 4);
            acc[0][0] = fma2(wv.x, pA.x, acc[0][0]);
            acc[0][1] = fma2(wv.x, pA.y, acc[0][1]);
            acc[0][2] = fma2(wv.x, pB.x, acc[0][2]);
            acc[0][3] = fma2(wv.x, pB.y, acc[0][3]);
            acc[1][0] = fma2(wv.y, pA.x, acc[1][0]);
            acc[1][1] = fma2(wv.y, pA.y, acc[1][1]);
            acc[1][2] = fma2(wv.y, pB.x, acc[1][2]);
            acc[1][3] = fma2(wv.y, pB.y, acc[1][3]);
        }

        if (pf) STS_STAGE(c + 1, nb);
        __syncthreads();
    }

    // ---- epilogue: add bias, write out[t][o] ----
    const float4 b4 = *(const float4*)(bias + go + o0);
    const float bv[4] = {b4.x, b4.y, b4.z, b4.w};
    #pragma unroll
    for (int op = 0; op < 2; ++op) {
        #pragma unroll
        for (int t = 0; t < 4; ++t) {
            float2 v;
            asm("mov.b64 {%0, %1}, %2;" : "=f"(v.x), "=f"(v.y) : "l"(acc[op][t]));
            int token = tg * 4 + t;
            int o = o0 + op * 2;
            out[token * OUT_F + go + o]     = v.x + bv[o];
            out[token * OUT_F + go + o + 1] = v.y + bv[o + 1];
        }
    }

    #undef LDG_STAGE
    #undef STS_STAGE
}

// ---------------------------------------------------------------------------
extern "C" void kernel_launch(void* const* d_in, const int* in_sizes, int n_in,
                              void* d_out, int out_size) {
    const float* input  = (const float*)d_in[0];
    const float* q_w    = (const float*)d_in[1];
    const float* fp_w   = (const float*)d_in[2];
    const float* alpha  = (const float*)d_in[3];
    const float* bias   = (const float*)d_in[4];
    const float* noise  = (const float*)d_in[5];
    const int*   inv    = (const int*)d_in[6];
    float* out = (float*)d_out;

    (void)in_sizes; (void)n_in; (void)out_size;

    static int smem_set = 0;
    const int smem_bytes = (2 * KC * NO + 2 * KC * INROW + NO) * (int)sizeof(float);
    if (!smem_set) {
        cudaFuncSetAttribute(linear_kernel,
                             cudaFuncAttributeMaxDynamicSharedMemorySize,
                             smem_bytes);
        smem_set = 1;
    }

    perm_kernel<<<IN_F / 256, 256>>>(input, inv);
    linear_kernel<<<OUT_F / NO, 256, smem_bytes>>>(q_w, fp_w, alpha, bias, noise, out);
}

// round 3
// speedup vs baseline: 1.3183x; 1.3183x over previous
#include <cuda_runtime.h>

#define TOKENS   64
#define IN_F     8192
#define OUT_F    8192
#define QIN      7936
#define OUTL     256

#define NO       64                  // out-features per CTA
#define KC       16                  // k per chunk (7936 % 16 == 0 -> chunks never straddle q/fp)
#define KSPLIT   8
#define KRANGE   (IN_F / KSPLIT)     // 1024
#define NCH      (KRANGE / KC)       // 64 chunks per CTA
#define WROW     128                 // w_s row: 64 outs duplicated = 128 floats
#define IROW     68                  // in_s row: 64 tokens + 4 pad (keeps rows 16B aligned)
#define NTILES   (OUT_F / NO)        // 128

// Scratch (device globals: no allocation allowed)
__device__ float g_perm_in[IN_F * TOKENS];            // [k][t]
__device__ float g_part[KSPLIT * TOKENS * OUT_F];     // [s][t][o]  8 MB

// ---------------------------------------------------------------------------
// Kernel 1: scatter input columns through inv_col_perm: perm_in[inv[j]][t]=in[t][j]
// ---------------------------------------------------------------------------
__global__ void perm_kernel(const float* __restrict__ inp,
                            const int* __restrict__ inv) {
    int j = blockIdx.x * blockDim.x + threadIdx.x;
    if (j < IN_F) {
        int dst = inv[j];
        #pragma unroll
        for (int t = 0; t < TOKENS; ++t)
            g_perm_in[dst * TOKENS + t] = inp[t * IN_F + j];
    }
}

// Packed f32x2 FMA
__device__ __forceinline__ unsigned long long fma2(unsigned long long a,
                                                   unsigned long long b,
                                                   unsigned long long c) {
    unsigned long long d;
    asm("fma.rn.f32x2 %0, %1, %2, %3;" : "=l"(d) : "l"(a), "l"(b), "l"(c));
    return d;
}

// ---------------------------------------------------------------------------
// Kernel 2: fused transform + GEMM partial.
// Grid 1024 = 128 out-tiles x 8 K-splits. Block 128.
// Compute thread: 1 out x 32 tokens (16 f32x2 accumulators).
// Weights staged to smem DUPLICATED as f32x2 pairs -> inner loop needs no MOVs.
// ---------------------------------------------------------------------------
__global__ void __launch_bounds__(128, 4)
linear_kernel(const float* __restrict__ q_w,
              const float* __restrict__ fp_w,
              const float* __restrict__ alpha,
              const float* __restrict__ noise) {
    __shared__ float w_s[2 * KC * WROW];    // 16 KB, [buf][k][2*o] dup pairs
    __shared__ float in_s[2 * KC * IROW];   // 8.5 KB, [buf][k][t]

    const int tid = threadIdx.x;
    const int ot  = blockIdx.x & (NTILES - 1);
    const int s   = blockIdx.x >> 7;
    const int go  = ot * NO;
    const int k0  = s * KRANGE;

    // staging roles
    const int srow  = tid >> 1;          // weight row 0..63
    const int shalf = tid & 1;           // 8 k's each
    const int ikr   = tid >> 3;          // input k-row 0..15
    const int ipart = tid & 7;           // 8 floats each

    // compute roles
    const int co = tid & 63;             // out within tile
    const int t0 = (tid >> 6) * 32;      // token base (0 or 32)

    const float av = alpha[go + srow];
    const float dh = av * (0.5f / 7.0f);

    unsigned long long acc[16];
    #pragma unroll
    for (int i = 0; i < 16; ++i) acc[i] = 0ull;

    float4 qv[2], nv[2], iv[2];

    #define LDG_STAGE(c)                                                       \
    {                                                                          \
        const int kb = k0 + (c) * KC;                                          \
        const int kk = kb + 8 * shalf;                                         \
        if (kb < QIN) {                                                        \
            const float* p = q_w + (size_t)(go + srow) * QIN + kk;             \
            qv[0] = *(const float4*)(p);                                       \
            qv[1] = *(const float4*)(p + 4);                                   \
            const float* n = noise + (size_t)(go + srow) * QIN + kk;           \
            nv[0] = *(const float4*)(n);                                       \
            nv[1] = *(const float4*)(n + 4);                                   \
        } else {                                                               \
            const float* p = fp_w + (size_t)(go + srow) * OUTL + (kk - QIN);   \
            qv[0] = *(const float4*)(p);                                       \
            qv[1] = *(const float4*)(p + 4);                                   \
        }                                                                      \
        const float* ip = g_perm_in + (size_t)(kb + ikr) * TOKENS + 8 * ipart; \
        iv[0] = *(const float4*)(ip);                                          \
        iv[1] = *(const float4*)(ip + 4);                                      \
    }

    #define STS_STAGE(c, b)                                                    \
    {                                                                          \
        const bool isq = (k0 + (c) * KC) < QIN;                                \
        float* wb = w_s + (b) * KC * WROW;                                     \
        float* ib = in_s + (b) * KC * IROW;                                    \
        _Pragma("unroll")                                                      \
        for (int m = 0; m < 2; ++m) {                                          \
            float v[4] = {qv[m].x, qv[m].y, qv[m].z, qv[m].w};                 \
            float n[4] = {nv[m].x, nv[m].y, nv[m].z, nv[m].w};                 \
            _Pragma("unroll")                                                  \
            for (int j = 0; j < 4; ++j) {                                      \
                float w = v[j];                                                \
                if (isq)                                                       \
                    w = (w >= av) ? av : ((w <= -av) ? -av : fmaf(n[j], dh, w));\
                int kl = 8 * shalf + 4 * m + j;                                \
                *(float2*)(wb + kl * WROW + 2 * srow) = make_float2(w, w);     \
            }                                                                  \
        }                                                                      \
        *(float4*)(ib + ikr * IROW + 8 * ipart)     = iv[0];                   \
        *(float4*)(ib + ikr * IROW + 8 * ipart + 4) = iv[1];                   \
    }

    // prologue
    LDG_STAGE(0);
    STS_STAGE(0, 0);
    __syncthreads();

    for (int c = 0; c < NCH; ++c) {
        const int cb = c & 1;
        const bool pf = (c + 1 < NCH);
        if (pf) LDG_STAGE(c + 1);

        const float* wb = w_s + cb * KC * WROW + 2 * co;
        const float* ib = in_s + cb * KC * IROW + t0;

        #pragma unroll 4
        for (int kk = 0; kk < KC; ++kk) {
            const unsigned long long wd =
                *(const unsigned long long*)(wb + kk * WROW);
            #pragma unroll
            for (int i = 0; i < 8; ++i) {
                const ulonglong2 p =
                    *(const ulonglong2*)(ib + kk * IROW + 4 * i);
                acc[2 * i]     = fma2(wd, p.x, acc[2 * i]);
                acc[2 * i + 1] = fma2(wd, p.y, acc[2 * i + 1]);
            }
        }

        if (pf) STS_STAGE(c + 1, cb ^ 1);
        __syncthreads();
    }

    // epilogue: write fp32 partials (coalesced: lanes along co)
    float* pp = g_part + (size_t)s * TOKENS * OUT_F + go + co;
    #pragma unroll
    for (int j = 0; j < 16; ++j) {
        float lo, hi;
        asm("mov.b64 {%0, %1}, %2;" : "=f"(lo), "=f"(hi) : "l"(acc[j]));
        int t = t0 + 2 * j;
        pp[(size_t)t * OUT_F]       = lo;
        pp[(size_t)(t + 1) * OUT_F] = hi;
    }

    #undef LDG_STAGE
    #undef STS_STAGE
}

// ---------------------------------------------------------------------------
// Kernel 3: reduce K-splits + bias.  out[t][o] = sum_s part[s][t][o] + bias[o]
// ---------------------------------------------------------------------------
__global__ void reduce_kernel(const float* __restrict__ bias,
                              float* __restrict__ out) {
    int i = blockIdx.x * blockDim.x + threadIdx.x;      // float4 index
    if (i < TOKENS * OUT_F / 4) {
        int idx = i * 4;
        int o = idx & (OUT_F - 1);
        float4 b = *(const float4*)(bias + o);
        float4 acc = make_float4(b.x, b.y, b.z, b.w);
        #pragma unroll
        for (int s = 0; s < KSPLIT; ++s) {
            float4 v = *(const float4*)(g_part + (size_t)s * TOKENS * OUT_F + idx);
            acc.x += v.x; acc.y += v.y; acc.z += v.z; acc.w += v.w;
        }
        *(float4*)(out + idx) = acc;
    }
}

// ---------------------------------------------------------------------------
extern "C" void kernel_launch(void* const* d_in, const int* in_sizes, int n_in,
                              void* d_out, int out_size) {
    const float* input  = (const float*)d_in[0];
    const float* q_w    = (const float*)d_in[1];
    const float* fp_w   = (const float*)d_in[2];
    const float* alpha  = (const float*)d_in[3];
    const float* bias   = (const float*)d_in[4];
    const float* noise  = (const float*)d_in[5];
    const int*   inv    = (const int*)d_in[6];
    float* out = (float*)d_out;

    (void)in_sizes; (void)n_in; (void)out_size;

    perm_kernel<<<IN_F / 256, 256>>>(input, inv);
    linear_kernel<<<NTILES * KSPLIT, 128>>>(q_w, fp_w, alpha, noise);
    reduce_kernel<<<(TOKENS * OUT_F / 4 + 255) / 256, 256>>>(bias, out);
}

// round 7
// speedup vs baseline: 2.4271x; 1.8411x over previous
#include <cuda_runtime.h>
#include <cuda_bf16.h>
#include <cstdint>

#define TOKENS   64
#define IN_F     8192
#define OUT_F    8192
#define QIN      7936
#define OUTL     256

#define MT       128                 // out-features per CTA
#define KSPLIT   4
#define KRANGE   (IN_F / KSPLIT)     // 2048
#define NSTEP    (KRANGE / 16)       // 128 k16 steps per CTA
#define NTILE    (OUT_F / MT)        // 64
#define NK16     (IN_F / 16)         // 512

// device scratch (no allocations allowed)
__device__ float g_perm_in[IN_F * TOKENS];          // [k][t] fp32
__device__ uint2 g_bfh[NK16 * 8 * 32];              // B hi fragments [k16][n][lane]
__device__ uint2 g_bfl[NK16 * 8 * 32];              // B lo fragments
__device__ float g_part[KSPLIT * TOKENS * OUT_F];   // 8 MB partials

// ---------------------------------------------------------------------------
// helpers
// ---------------------------------------------------------------------------
__device__ __forceinline__ uint32_t pack_bf16x2(float hi_elem, float lo_elem) {
    uint32_t d;
    asm("cvt.rn.bf16x2.f32 %0, %1, %2;" : "=r"(d) : "f"(hi_elem), "f"(lo_elem));
    return d;
}
// split (v0 -> low half, v1 -> high half) into bf16 hi and residual lo packs
__device__ __forceinline__ void split2(float v0, float v1,
                                       uint32_t& h, uint32_t& l) {
    h = pack_bf16x2(v1, v0);
    float h0 = __uint_as_float(h << 16);
    float h1 = __uint_as_float(h & 0xFFFF0000u);
    l = pack_bf16x2(v1 - h1, v0 - h0);
}
__device__ __forceinline__ void mma_bf16(float* c,
                                         uint32_t a0, uint32_t a1,
                                         uint32_t a2, uint32_t a3,
                                         uint32_t b0, uint32_t b1) {
    asm volatile(
        "mma.sync.aligned.m16n8k16.row.col.f32.bf16.bf16.f32 "
        "{%0,%1,%2,%3}, {%4,%5,%6,%7}, {%8,%9}, {%0,%1,%2,%3};"
        : "+f"(c[0]), "+f"(c[1]), "+f"(c[2]), "+f"(c[3])
        : "r"(a0), "r"(a1), "r"(a2), "r"(a3), "r"(b0), "r"(b1));
}

// ---------------------------------------------------------------------------
// Kernel 1: permuted input, smem-staged: g_perm_in[inv[j]][t] = input[t][j]
// ---------------------------------------------------------------------------
__global__ void __launch_bounds__(256)
perm_kernel(const float* __restrict__ inp, const int* __restrict__ inv) {
    __shared__ float tile[64][65];
    __shared__ int   dsts[64];
    const int tid = threadIdx.x;
    const int jb  = blockIdx.x * 64;
    const int jj  = tid & 63, tq = tid >> 6;
    #pragma unroll
    for (int i = 0; i < 16; ++i) {
        int t = tq * 16 + i;
        tile[jj][t] = inp[(size_t)t * IN_F + jb + jj];
    }
    if (tid < 64) dsts[tid] = inv[jb + tid];
    __syncthreads();
    const int wjj = tid >> 2, wq = tid & 3;
    const int dst = dsts[wjj];
    float* op = g_perm_in + (size_t)dst * TOKENS + wq * 16;
    #pragma unroll
    for (int i = 0; i < 4; ++i) {
        int t = wq * 16 + i * 4;
        *(float4*)(op + i * 4) = make_float4(tile[wjj][t], tile[wjj][t + 1],
                                             tile[wjj][t + 2], tile[wjj][t + 3]);
    }
}

// ---------------------------------------------------------------------------
// Kernel 2: pack B (input) into per-lane bf16 hi/lo MMA fragments.
// For (k16, n, lane): g=lane>>2, tg=lane&3, t=n*8+g
//   b0 = {B[k16*16+tg*2][t], B[..+1][t]}, b1 = same at k+8.
// ---------------------------------------------------------------------------
__global__ void __launch_bounds__(256)
prep_b_kernel() {
    __shared__ float tile[64][68];          // stride 68 keeps float4 rows aligned
    const int tid = threadIdx.x;
    const int kb  = blockIdx.x * 64;
    {
        const int row = tid >> 2, q4 = tid & 3;
        const float4* src = (const float4*)(g_perm_in + (size_t)(kb + row) * TOKENS + q4 * 16);
        float4 v0 = src[0], v1 = src[1], v2 = src[2], v3 = src[3];
        *(float4*)&tile[row][q4 * 16]      = v0;
        *(float4*)&tile[row][q4 * 16 + 4]  = v1;
        *(float4*)&tile[row][q4 * 16 + 8]  = v2;
        *(float4*)&tile[row][q4 * 16 + 12] = v3;
    }
    __syncthreads();
    const int lane = tid & 31, n = tid >> 5;
    const int g = lane >> 2, tg = lane & 3;
    const int t = n * 8 + g;
    #pragma unroll
    for (int k16l = 0; k16l < 4; ++k16l) {
        const int kl = k16l * 16 + tg * 2;
        float v00 = tile[kl][t],     v01 = tile[kl + 1][t];
        float v10 = tile[kl + 8][t], v11 = tile[kl + 9][t];
        uint32_t b0h, b0l, b1h, b1l;
        split2(v00, v01, b0h, b0l);
        split2(v10, v11, b1h, b1l);
        size_t idx = (((size_t)(blockIdx.x * 4 + k16l)) * 8 + n) * 32 + lane;
        g_bfh[idx] = make_uint2(b0h, b1h);
        g_bfl[idx] = make_uint2(b0l, b1l);
    }
}

// ---------------------------------------------------------------------------
// Kernel 3: fused weight transform + HMMA bf16 hi/lo GEMM partial.
// Grid 256 = 64 out-tiles x 4 K-splits. 256 threads, no smem, 2 CTAs/SM.
// Warp: M=16 rows x N=64 tokens (8 m16n8k16 tiles, 3 MMA terms each).
// A fragments loaded straight from GMEM (fp32), transformed + split in regs.
// ---------------------------------------------------------------------------
__global__ void __launch_bounds__(256, 2)
linear_kernel(const float* __restrict__ q_w, const float* __restrict__ fp_w,
              const float* __restrict__ alpha, const float* __restrict__ noise) {
    const int tid  = threadIdx.x;
    const int wid  = tid >> 5;
    const int lane = tid & 31;
    const int g    = lane >> 2;
    const int tg   = lane & 3;
    const int ot   = blockIdx.x >> 2;
    const int s    = blockIdx.x & 3;
    const int go   = ot * MT;
    const int k0   = s * KRANGE;
    const int R0   = go + wid * 16 + g;      // fragment rows R0 and R0+8
    const int koff = tg * 2;

    const float a0v = alpha[R0];
    const float a1v = alpha[R0 + 8];
    const float dh0 = a0v * (0.5f / 7.0f);
    const float dh1 = a1v * (0.5f / 7.0f);

    const float* qp0 = q_w   + (size_t)R0 * QIN;
    const float* qp1 = qp0   + (size_t)8 * QIN;
    const float* np0 = noise + (size_t)R0 * QIN;
    const float* np1 = np0   + (size_t)8 * QIN;
    const float* fp0 = fp_w  + (size_t)R0 * OUTL;
    const float* fp1 = fp0   + (size_t)8 * OUTL;
    const uint2* bfh = g_bfh + (size_t)(k0 >> 4) * 256 + lane;
    const uint2* bfl = g_bfl + (size_t)(k0 >> 4) * 256 + lane;

    float acc[8][4];
    #pragma unroll
    for (int n = 0; n < 8; ++n)
        #pragma unroll
        for (int i = 0; i < 4; ++i) acc[n][i] = 0.0f;

    float2 q00, q01, q10, q11;
    float2 n00 = {0, 0}, n01 = {0, 0}, n10 = {0, 0}, n11 = {0, 0};

    #define LDA(kb)                                                        \
    {                                                                      \
        if ((kb) < QIN) {                                                  \
            q00 = *(const float2*)(qp0 + (kb) + koff);                     \
            q01 = *(const float2*)(qp0 + (kb) + koff + 8);                 \
            q10 = *(const float2*)(qp1 + (kb) + koff);                     \
            q11 = *(const float2*)(qp1 + (kb) + koff + 8);                 \
            n00 = *(const float2*)(np0 + (kb) + koff);                     \
            n01 = *(const float2*)(np0 + (kb) + koff + 8);                 \
            n10 = *(const float2*)(np1 + (kb) + koff);                     \
            n11 = *(const float2*)(np1 + (kb) + koff + 8);                 \
        } else {                                                           \
            const int kf = (kb) - QIN;                                     \
            q00 = *(const float2*)(fp0 + kf + koff);                       \
            q01 = *(const float2*)(fp0 + kf + koff + 8);                   \
            q10 = *(const float2*)(fp1 + kf + koff);                       \
            q11 = *(const float2*)(fp1 + kf + koff + 8);                   \
        }                                                                  \
    }

    LDA(k0);                       // preload step 0

    #pragma unroll 2
    for (int c = 0; c < NSTEP; ++c) {
        // B fragments for this step (coalesced LDG.64, L2-resident)
        uint2 bh[8], bl[8];
        #pragma unroll
        for (int n = 0; n < 8; ++n) {
            bh[n] = bfh[(size_t)c * 256 + n * 32];
            bl[n] = bfl[(size_t)c * 256 + n * 32];
        }

        const bool isq = (k0 + c * 16) < QIN;

        // transform current A (clamp / noise) -> hi/lo bf16 fragments
        float w[8] = {q00.x, q00.y, q01.x, q01.y, q10.x, q10.y, q11.x, q11.y};
        if (isq) {
            const float nn[8] = {n00.x, n00.y, n01.x, n01.y,
                                 n10.x, n10.y, n11.x, n11.y};
            #pragma unroll
            for (int e = 0; e < 8; ++e) {
                const float a  = (e < 4) ? a0v : a1v;
                const float dh = (e < 4) ? dh0 : dh1;
                float v = w[e];
                w[e] = (v >= a) ? a : ((v <= -a) ? -a : fmaf(nn[e], dh, v));
            }
        }
        uint32_t ah[4], al[4];
        split2(w[0], w[1], ah[0], al[0]);   // (R0,   k)
        split2(w[4], w[5], ah[1], al[1]);   // (R0+8, k)
        split2(w[2], w[3], ah[2], al[2]);   // (R0,   k+8)
        split2(w[6], w[7], ah[3], al[3]);   // (R0+8, k+8)

        // prefetch next step's A raw data
        {
            const int cn = (c + 1 < NSTEP) ? c + 1 : c;
            const int kb = k0 + cn * 16;
            LDA(kb);
        }

        // 3-term hi/lo MMAs
        #pragma unroll
        for (int n = 0; n < 8; ++n) {
            mma_bf16(acc[n], ah[0], ah[1], ah[2], ah[3], bh[n].x, bh[n].y);
            mma_bf16(acc[n], ah[0], ah[1], ah[2], ah[3], bl[n].x, bl[n].y);
            mma_bf16(acc[n], al[0], al[1], al[2], al[3], bh[n].x, bh[n].y);
        }
    }
    #undef LDA

    // epilogue: partials to g_part[s][t][o]
    float* pp = g_part + (size_t)s * TOKENS * OUT_F;
    #pragma unroll
    for (int n = 0; n < 8; ++n) {
        const int t = n * 8 + tg * 2;
        pp[(size_t)t * OUT_F + R0]           = acc[n][0];
        pp[(size_t)(t + 1) * OUT_F + R0]     = acc[n][1];
        pp[(size_t)t * OUT_F + R0 + 8]       = acc[n][2];
        pp[(size_t)(t + 1) * OUT_F + R0 + 8] = acc[n][3];
    }
}

// ---------------------------------------------------------------------------
// Kernel 4: reduce K-splits + bias
// ---------------------------------------------------------------------------
__global__ void __launch_bounds__(256)
reduce_kernel(const float* __restrict__ bias, float* __restrict__ out) {
    int i = blockIdx.x * blockDim.x + threadIdx.x;
    if (i < TOKENS * OUT_F / 4) {
        int idx = i * 4;
        int o = idx & (OUT_F - 1);
        float4 b = *(const float4*)(bias + o);
        float4 acc = b;
        #pragma unroll
        for (int s = 0; s < KSPLIT; ++s) {
            float4 v = *(const float4*)(g_part + (size_t)s * TOKENS * OUT_F + idx);
            acc.x += v.x; acc.y += v.y; acc.z += v.z; acc.w += v.w;
        }
        *(float4*)(out + idx) = acc;
    }
}

// ---------------------------------------------------------------------------
extern "C" void kernel_launch(void* const* d_in, const int* in_sizes, int n_in,
                              void* d_out, int out_size) {
    const float* input  = (const float*)d_in[0];
    const float* q_w    = (const float*)d_in[1];
    const float* fp_w   = (const float*)d_in[2];
    const float* alpha  = (const float*)d_in[3];
    const float* bias   = (const float*)d_in[4];
    const float* noise  = (const float*)d_in[5];
    const int*   inv    = (const int*)d_in[6];
    float* out = (float*)d_out;
    (void)in_sizes; (void)n_in; (void)out_size;

    perm_kernel<<<IN_F / 64, 256>>>(input, inv);
    prep_b_kernel<<<IN_F / 64, 256>>>();
    linear_kernel<<<NTILE * KSPLIT, 256>>>(q_w, fp_w, alpha, noise);
    reduce_kernel<<<(TOKENS * OUT_F / 4 + 255) / 256, 256>>>(bias, out);
}

// round 8
// speedup vs baseline: 3.1447x; 1.2957x over previous
#include <cuda_runtime.h>
#include <cuda_bf16.h>
#include <cstdint>

#define TOKENS   64
#define IN_F     8192
#define OUT_F    8192
#define QIN      7936
#define OUTL     256

#define MT       128                 // out-features per tile (MMA M per CTA slice)
#define TILES    (OUT_F / MT)        // 64
#define NK16T    (IN_F / 16)         // 512 k16 steps per tile
#define TOTAL    (TILES * NK16T)     // 32768 global work units

// device scratch (no allocations allowed)
__device__ int   g_fwd[IN_F];                 // forward column permutation
__device__ uint4 g_bf[NK16T * 8 * 32];        // B frags [k16][n][lane] {b0h,b1h,b0l,b1l}

// ---------------------------------------------------------------------------
// helpers
// ---------------------------------------------------------------------------
__device__ __forceinline__ uint32_t pack_bf16x2(float hi_elem, float lo_elem) {
    uint32_t d;
    asm("cvt.rn.bf16x2.f32 %0, %1, %2;" : "=r"(d) : "f"(hi_elem), "f"(lo_elem));
    return d;
}
// split (v0 -> low half, v1 -> high half) into bf16 hi and residual lo packs
__device__ __forceinline__ void split2(float v0, float v1,
                                       uint32_t& h, uint32_t& l) {
    h = pack_bf16x2(v1, v0);
    float h0 = __uint_as_float(h << 16);
    float h1 = __uint_as_float(h & 0xFFFF0000u);
    l = pack_bf16x2(v1 - h1, v0 - h0);
}
__device__ __forceinline__ void mma_bf16(float* c,
                                         uint32_t a0, uint32_t a1,
                                         uint32_t a2, uint32_t a3,
                                         uint32_t b0, uint32_t b1) {
    asm volatile(
        "mma.sync.aligned.m16n8k16.row.col.f32.bf16.bf16.f32 "
        "{%0,%1,%2,%3}, {%4,%5,%6,%7}, {%8,%9}, {%0,%1,%2,%3};"
        : "+f"(c[0]), "+f"(c[1]), "+f"(c[2]), "+f"(c[3])
        : "r"(a0), "r"(a1), "r"(a2), "r"(a3), "r"(b0), "r"(b1));
}

// ---------------------------------------------------------------------------
// Kernel 1: forward permutation  g_fwd[inv[j]] = j
// ---------------------------------------------------------------------------
__global__ void fwd_kernel(const int* __restrict__ inv) {
    int j = blockIdx.x * blockDim.x + threadIdx.x;
    if (j < IN_F) g_fwd[inv[j]] = j;
}

// ---------------------------------------------------------------------------
// Kernel 2: init output with bias (accumulation target for RED.ADD)
// ---------------------------------------------------------------------------
__global__ void __launch_bounds__(256)
init_out_kernel(const float* __restrict__ bias, float* __restrict__ out) {
    int i = blockIdx.x * blockDim.x + threadIdx.x;      // float4 index
    int idx = i * 4;
    int o = idx & (OUT_F - 1);
    *(float4*)(out + idx) = *(const float4*)(bias + o);
}

// ---------------------------------------------------------------------------
// Kernel 3: gather permuted input + pack bf16 hi/lo MMA B-fragments.
// For (k16, n, lane): g=lane>>2, tg=lane&3, t=n*8+g
//   b0 = {B[k16*16+tg*2][t], B[..+1][t]}, b1 = same at k+8.
// ---------------------------------------------------------------------------
__global__ void __launch_bounds__(256)
prep_b_kernel(const float* __restrict__ inp) {
    __shared__ float tile[64][68];
    __shared__ int   jcol[64];
    const int tid = threadIdx.x;
    const int kb  = blockIdx.x * 64;

    if (tid < 64) jcol[tid] = g_fwd[kb + tid];
    __syncthreads();
    {
        const int k = tid >> 2, tq = tid & 3;
        const int j = jcol[k];
        #pragma unroll
        for (int i = 0; i < 16; ++i) {
            int t = tq * 16 + i;
            tile[k][t] = inp[(size_t)t * IN_F + j];
        }
    }
    __syncthreads();

    const int lane = tid & 31, n = tid >> 5;
    const int g = lane >> 2, tg = lane & 3;
    const int t = n * 8 + g;
    #pragma unroll
    for (int k16l = 0; k16l < 4; ++k16l) {
        const int kl = k16l * 16 + tg * 2;
        uint32_t b0h, b0l, b1h, b1l;
        split2(tile[kl][t],     tile[kl + 1][t], b0h, b0l);
        split2(tile[kl + 8][t], tile[kl + 9][t], b1h, b1l);
        g_bf[(size_t)(blockIdx.x * 4 + k16l) * 256 + n * 32 + lane] =
            make_uint4(b0h, b1h, b0l, b1l);
    }
}

// ---------------------------------------------------------------------------
// Kernel 4: persistent balanced fused transform + HMMA GEMM.
// Grid = 2*SMs CTAs, 256 threads. Global step space [0, TOTAL) split evenly;
// step S -> (tile = S>>9, k16 = S&511). B staged via smem (double buffer).
// Accumulators flushed by RED.ADD into bias-initialized out.
// ---------------------------------------------------------------------------
__global__ void __launch_bounds__(256, 2)
linear_kernel(const float* __restrict__ q_w, const float* __restrict__ fp_w,
              const float* __restrict__ alpha, const float* __restrict__ noise,
              float* __restrict__ out) {
    __shared__ uint4 sB[2][256];

    const int tid  = threadIdx.x;
    const int wid  = tid >> 5;
    const int lane = tid & 31;
    const int g    = lane >> 2;
    const int tg   = lane & 3;
    const int koff = tg * 2;
    const int mrow = wid * 16 + g;           // row within tile (and +8)

    const int s_begin = (int)(((long long)TOTAL * blockIdx.x) / gridDim.x);
    const int s_end   = (int)(((long long)TOTAL * (blockIdx.x + 1)) / gridDim.x);
    const int i_end   = s_end - s_begin;

    float2 q00, q01, q10, q11;
    float2 n00 = {0, 0}, n01 = {0, 0}, n10 = {0, 0}, n11 = {0, 0};

    #define LDA(S_)                                                            \
    {                                                                          \
        const int kb_ = ((S_) & (NK16T - 1)) * 16;                             \
        const int R0_ = ((S_) >> 9) * MT + mrow;                               \
        if (kb_ < QIN) {                                                       \
            const float* qp = q_w   + (size_t)R0_ * QIN + kb_ + koff;          \
            const float* np = noise + (size_t)R0_ * QIN + kb_ + koff;          \
            q00 = *(const float2*)(qp);                                        \
            q01 = *(const float2*)(qp + 8);                                    \
            q10 = *(const float2*)(qp + (size_t)8 * QIN);                      \
            q11 = *(const float2*)(qp + (size_t)8 * QIN + 8);                  \
            n00 = *(const float2*)(np);                                        \
            n01 = *(const float2*)(np + 8);                                    \
            n10 = *(const float2*)(np + (size_t)8 * QIN);                      \
            n11 = *(const float2*)(np + (size_t)8 * QIN + 8);                  \
        } else {                                                               \
            const float* fp = fp_w + (size_t)R0_ * OUTL + (kb_ - QIN) + koff;  \
            q00 = *(const float2*)(fp);                                        \
            q01 = *(const float2*)(fp + 8);                                    \
            q10 = *(const float2*)(fp + (size_t)8 * OUTL);                     \
            q11 = *(const float2*)(fp + (size_t)8 * OUTL + 8);                 \
        }                                                                      \
    }

    float acc[8][4];
    #pragma unroll
    for (int n = 0; n < 8; ++n)
        #pragma unroll
        for (int i = 0; i < 4; ++i) acc[n][i] = 0.0f;

    #define FLUSH(tile_)                                                       \
    {                                                                          \
        const int Rf = (tile_) * MT + mrow;                                    \
        _Pragma("unroll")                                                      \
        for (int n = 0; n < 8; ++n) {                                          \
            const int t = n * 8 + tg * 2;                                      \
            atomicAdd(out + (size_t)t * OUT_F + Rf,           acc[n][0]);      \
            atomicAdd(out + (size_t)(t + 1) * OUT_F + Rf,     acc[n][1]);      \
            atomicAdd(out + (size_t)t * OUT_F + Rf + 8,       acc[n][2]);      \
            atomicAdd(out + (size_t)(t + 1) * OUT_F + Rf + 8, acc[n][3]);      \
        }                                                                      \
    }

    // prologue: A regs + B smem for first step
    LDA(s_begin);
    sB[0][tid] = g_bf[(size_t)(s_begin & (NK16T - 1)) * 256 + tid];
    __syncthreads();

    int cur_tile = s_begin >> 9;
    float a0v = alpha[cur_tile * MT + mrow];
    float a1v = alpha[cur_tile * MT + mrow + 8];
    float dh0 = a0v * (0.5f / 7.0f);
    float dh1 = a1v * (0.5f / 7.0f);

    for (int i = 0; i < i_end; ++i) {
        const int S = s_begin + i;
        const int tile = S >> 9;
        if (tile != cur_tile) {
            FLUSH(cur_tile);
            #pragma unroll
            for (int n = 0; n < 8; ++n)
                #pragma unroll
                for (int j = 0; j < 4; ++j) acc[n][j] = 0.0f;
            a0v = alpha[tile * MT + mrow];
            a1v = alpha[tile * MT + mrow + 8];
            dh0 = a0v * (0.5f / 7.0f);
            dh1 = a1v * (0.5f / 7.0f);
            cur_tile = tile;
        }

        // fetch next step's B fragment (global, coalesced LDG.128)
        const bool hn = (i + 1 < i_end);
        uint4 nb;
        if (hn) nb = g_bf[(size_t)((S + 1) & (NK16T - 1)) * 256 + tid];

        // transform current A (clamp / noise) -> hi/lo bf16 fragments
        const bool isq = ((S & (NK16T - 1)) * 16) < QIN;
        float w[8] = {q00.x, q00.y, q01.x, q01.y, q10.x, q10.y, q11.x, q11.y};
        if (isq) {
            const float nn[8] = {n00.x, n00.y, n01.x, n01.y,
                                 n10.x, n10.y, n11.x, n11.y};
            #pragma unroll
            for (int e = 0; e < 8; ++e) {
                const float a  = (e < 4) ? a0v : a1v;
                const float dh = (e < 4) ? dh0 : dh1;
                float v = w[e];
                w[e] = (v >= a) ? a : ((v <= -a) ? -a : fmaf(nn[e], dh, v));
            }
        }
        uint32_t ah[4], al[4];
        split2(w[0], w[1], ah[0], al[0]);   // (R0,   k)
        split2(w[4], w[5], ah[1], al[1]);   // (R0+8, k)
        split2(w[2], w[3], ah[2], al[2]);   // (R0,   k+8)
        split2(w[6], w[7], ah[3], al[3]);   // (R0+8, k+8)

        // prefetch next step's raw A while MMAs run
        if (hn) LDA(S + 1);

        // 3-term hi/lo MMAs; B from smem (one LDS.128 per n)
        const uint4* bb = sB[i & 1];
        #pragma unroll
        for (int n = 0; n < 8; ++n) {
            const uint4 bv = bb[n * 32 + lane];
            mma_bf16(acc[n], ah[0], ah[1], ah[2], ah[3], bv.x, bv.y);
            mma_bf16(acc[n], ah[0], ah[1], ah[2], ah[3], bv.z, bv.w);
            mma_bf16(acc[n], al[0], al[1], al[2], al[3], bv.x, bv.y);
        }

        if (hn) sB[(i + 1) & 1][tid] = nb;
        __syncthreads();
    }

    FLUSH(cur_tile);

    #undef LDA
    #undef FLUSH
}

// ---------------------------------------------------------------------------
extern "C" void kernel_launch(void* const* d_in, const int* in_sizes, int n_in,
                              void* d_out, int out_size) {
    const float* input  = (const float*)d_in[0];
    const float* q_w    = (const float*)d_in[1];
    const float* fp_w   = (const float*)d_in[2];
    const float* alpha  = (const float*)d_in[3];
    const float* bias   = (const float*)d_in[4];
    const float* noise  = (const float*)d_in[5];
    const int*   inv    = (const int*)d_in[6];
    float* out = (float*)d_out;
    (void)in_sizes; (void)n_in; (void)out_size;

    static int nsm = 0;
    if (!nsm) {
        cudaDeviceGetAttribute(&nsm, cudaDevAttrMultiProcessorCount, 0);
        if (nsm <= 0) nsm = 148;
    }

    fwd_kernel<<<IN_F / 256, 256>>>(inv);
    init_out_kernel<<<TOKENS * OUT_F / 4 / 256, 256>>>(bias, out);
    prep_b_kernel<<<IN_F / 64, 256>>>(input);
    linear_kernel<<<2 * nsm, 256>>>(q_w, fp_w, alpha, noise, out);
}

// round 9
// speedup vs baseline: 3.9639x; 1.2605x over previous
#include <cuda_runtime.h>
#include <cuda_bf16.h>
#include <cstdint>

#define TOKENS   64
#define IN_F     8192
#define OUT_F    8192
#define QIN      7936
#define OUTL     256

#define MT       128                 // out-features per tile
#define TILES    (OUT_F / MT)        // 64
#define NK16T    (IN_F / 16)         // 512 k16 steps per tile
#define TOTAL    (TILES * NK16T)     // 32768 work units

#define STAGES   4
#define Q_OFF    0                   // float offsets within a stage
#define N_OFF    2048
#define B_OFF    4096
#define STAGE_F  5120                // floats per stage (20 KB)
#define SMEM_BYTES (STAGES * STAGE_F * 4)   // 81920 B

// device scratch (no allocations allowed)
__device__ int   g_fwd[IN_F];                 // forward column permutation
__device__ uint4 g_bf[NK16T * 8 * 32];        // B frags [k16][n][lane] {b0h,b1h,b0l,b1l}

// ---------------------------------------------------------------------------
// helpers
// ---------------------------------------------------------------------------
__device__ __forceinline__ uint32_t pack_bf16x2(float hi_elem, float lo_elem) {
    uint32_t d;
    asm("cvt.rn.bf16x2.f32 %0, %1, %2;" : "=r"(d) : "f"(hi_elem), "f"(lo_elem));
    return d;
}
// split (v0 -> low half, v1 -> high half) into bf16 hi and residual lo packs
__device__ __forceinline__ void split2(float v0, float v1,
                                       uint32_t& h, uint32_t& l) {
    h = pack_bf16x2(v1, v0);
    float h0 = __uint_as_float(h << 16);
    float h1 = __uint_as_float(h & 0xFFFF0000u);
    l = pack_bf16x2(v1 - h1, v0 - h0);
}
__device__ __forceinline__ void mma_bf16(float* c,
                                         uint32_t a0, uint32_t a1,
                                         uint32_t a2, uint32_t a3,
                                         uint32_t b0, uint32_t b1) {
    asm volatile(
        "mma.sync.aligned.m16n8k16.row.col.f32.bf16.bf16.f32 "
        "{%0,%1,%2,%3}, {%4,%5,%6,%7}, {%8,%9}, {%0,%1,%2,%3};"
        : "+f"(c[0]), "+f"(c[1]), "+f"(c[2]), "+f"(c[3])
        : "r"(a0), "r"(a1), "r"(a2), "r"(a3), "r"(b0), "r"(b1));
}
__device__ __forceinline__ void cp16(uint32_t dst, const void* src) {
    asm volatile("cp.async.cg.shared.global [%0], [%1], 16;"
                 :: "r"(dst), "l"(src));
}
__device__ __forceinline__ void cp_commit() {
    asm volatile("cp.async.commit_group;" ::: "memory");
}
__device__ __forceinline__ void cp_wait2() {
    asm volatile("cp.async.wait_group 2;" ::: "memory");
}
__device__ __forceinline__ uint32_t smem_u32(const void* p) {
    uint32_t a;
    asm("{ .reg .u64 t; cvta.to.shared.u64 t, %1; cvt.u32.u64 %0, t; }"
        : "=r"(a) : "l"(p));
    return a;
}

// ---------------------------------------------------------------------------
// Kernel 1: forward permutation  g_fwd[inv[j]] = j
// ---------------------------------------------------------------------------
__global__ void fwd_kernel(const int* __restrict__ inv) {
    int j = blockIdx.x * blockDim.x + threadIdx.x;
    if (j < IN_F) g_fwd[inv[j]] = j;
}

// ---------------------------------------------------------------------------
// Kernel 2: init output with bias (accumulation target for RED.ADD)
// ---------------------------------------------------------------------------
__global__ void __launch_bounds__(256)
init_out_kernel(const float* __restrict__ bias, float* __restrict__ out) {
    int i = blockIdx.x * blockDim.x + threadIdx.x;      // float4 index
    int idx = i * 4;
    int o = idx & (OUT_F - 1);
    *(float4*)(out + idx) = *(const float4*)(bias + o);
}

// ---------------------------------------------------------------------------
// Kernel 3: gather permuted input + pack bf16 hi/lo MMA B-fragments.
// k-PERMUTED layout: physical k 4tg+{0,1} -> logical frag slots 2tg,2tg+1 (b0),
// physical 4tg+{2,3} -> logical 2tg+8,2tg+9 (b1). A uses the same mapping,
// so the GEMM result is unchanged while A loads become contiguous float4s.
// ---------------------------------------------------------------------------
__global__ void __launch_bounds__(256)
prep_b_kernel(const float* __restrict__ inp) {
    __shared__ float tile[64][68];
    __shared__ int   jcol[64];
    const int tid = threadIdx.x;
    const int kb  = blockIdx.x * 64;

    if (tid < 64) jcol[tid] = g_fwd[kb + tid];
    __syncthreads();
    {
        const int k = tid >> 2, tq = tid & 3;
        const int j = jcol[k];
        #pragma unroll
        for (int i = 0; i < 16; ++i) {
            int t = tq * 16 + i;
            tile[k][t] = inp[(size_t)t * IN_F + j];
        }
    }
    __syncthreads();

    const int lane = tid & 31, n = tid >> 5;
    const int g = lane >> 2, tg = lane & 3;
    const int t = n * 8 + g;
    #pragma unroll
    for (int k16l = 0; k16l < 4; ++k16l) {
        const int kl = k16l * 16 + tg * 4;     // permuted: contiguous quad
        uint32_t b0h, b0l, b1h, b1l;
        split2(tile[kl][t],     tile[kl + 1][t], b0h, b0l);
        split2(tile[kl + 2][t], tile[kl + 3][t], b1h, b1l);
        g_bf[(size_t)(blockIdx.x * 4 + k16l) * 256 + n * 32 + lane] =
            make_uint4(b0h, b1h, b0l, b1l);
    }
}

// ---------------------------------------------------------------------------
// Kernel 4: persistent fused transform + HMMA GEMM, 4-stage cp.async pipeline.
// Grid = 2*SMs, 256 threads, 2 CTAs/SM. Step S -> (tile=S>>9, k16=S&511).
// Per stage: q 8KB + noise 8KB + B frags 4KB, all via cp.async.cg.
// Conflict-free LDS.128 consumption (row stride 64B + k-permuted fragments).
// ---------------------------------------------------------------------------
__global__ void __launch_bounds__(256, 2)
linear_kernel(const float* __restrict__ q_w, const float* __restrict__ fp_w,
              const float* __restrict__ alpha, const float* __restrict__ noise,
              float* __restrict__ out) {
    extern __shared__ float sm[];
    const uint32_t sb = smem_u32(sm);

    const int tid  = threadIdx.x;
    const int wid  = tid >> 5;
    const int lane = tid & 31;
    const int g    = lane >> 2;
    const int tg   = lane & 3;
    const int mrow = wid * 16 + g;          // rows mrow and mrow+8 within tile
    const int crow = tid >> 2;              // staging: row 0..63 (x2 halves)
    const int cqt  = tid & 3;               // staging: 16B quarter

    const int s_begin = (int)(((long long)TOTAL * blockIdx.x) / gridDim.x);
    const int s_end   = (int)(((long long)TOTAL * (blockIdx.x + 1)) / gridDim.x);
    const int i_end   = s_end - s_begin;

    #define ISSUE(S_)                                                          \
    {                                                                          \
        const int ii_ = (S_) - s_begin;                                        \
        const uint32_t st_ = sb + (uint32_t)((ii_ & 3) * (STAGE_F * 4));       \
        const int kb_ = ((S_) & (NK16T - 1)) * 16;                             \
        const int tb_ = ((S_) >> 9) * MT;                                      \
        if (kb_ < QIN) {                                                       \
            _Pragma("unroll")                                                  \
            for (int h = 0; h < 2; ++h) {                                      \
                const int row_ = crow + h * 64;                                \
                const uint32_t d_ = st_ + (uint32_t)((row_ * 16 + cqt * 4) * 4);\
                const size_t go_ = (size_t)(tb_ + row_) * QIN + kb_ + cqt * 4; \
                cp16(d_, q_w + go_);                                           \
                cp16(d_ + N_OFF * 4, noise + go_);                             \
            }                                                                  \
        } else {                                                               \
            _Pragma("unroll")                                                  \
            for (int h = 0; h < 2; ++h) {                                      \
                const int row_ = crow + h * 64;                                \
                const uint32_t d_ = st_ + (uint32_t)((row_ * 16 + cqt * 4) * 4);\
                cp16(d_, fp_w + (size_t)(tb_ + row_) * OUTL + (kb_ - QIN) + cqt * 4);\
            }                                                                  \
        }                                                                      \
        cp16(st_ + (uint32_t)(B_OFF * 4 + tid * 16),                           \
             g_bf + (size_t)((S_) & (NK16T - 1)) * 256 + tid);                 \
        cp_commit();                                                           \
    }

    float acc[8][4];
    #pragma unroll
    for (int n = 0; n < 8; ++n)
        #pragma unroll
        for (int j = 0; j < 4; ++j) acc[n][j] = 0.0f;

    #define FLUSH(tile_)                                                       \
    {                                                                          \
        const int Rf = (tile_) * MT + mrow;                                    \
        _Pragma("unroll")                                                      \
        for (int n = 0; n < 8; ++n) {                                          \
            const int t = n * 8 + tg * 2;                                      \
            atomicAdd(out + (size_t)t * OUT_F + Rf,           acc[n][0]);      \
            atomicAdd(out + (size_t)(t + 1) * OUT_F + Rf,     acc[n][1]);      \
            atomicAdd(out + (size_t)t * OUT_F + Rf + 8,       acc[n][2]);      \
            atomicAdd(out + (size_t)(t + 1) * OUT_F + Rf + 8, acc[n][3]);      \
        }                                                                      \
    }

    // prologue: issue 3 stages
    ISSUE(s_begin);
    ISSUE(s_begin + 1);
    ISSUE(s_begin + 2);

    int cur_tile = s_begin >> 9;
    float a0v = alpha[cur_tile * MT + mrow];
    float a1v = alpha[cur_tile * MT + mrow + 8];
    float dh0 = a0v * (0.5f / 7.0f);
    float dh1 = a1v * (0.5f / 7.0f);

    for (int i = 0; i < i_end; ++i) {
        const int S = s_begin + i;
        const int tile = S >> 9;
        if (tile != cur_tile) {
            FLUSH(cur_tile);
            #pragma unroll
            for (int n = 0; n < 8; ++n)
                #pragma unroll
                for (int j = 0; j < 4; ++j) acc[n][j] = 0.0f;
            a0v = alpha[tile * MT + mrow];
            a1v = alpha[tile * MT + mrow + 8];
            dh0 = a0v * (0.5f / 7.0f);
            dh1 = a1v * (0.5f / 7.0f);
            cur_tile = tile;
        }

        cp_wait2();               // stage i landed
        __syncthreads();          // visible to all warps; prior consume done

        if (i + 3 < i_end) { ISSUE(S + 3); } else { cp_commit(); }

        // ---- consume stage i ----
        const float* st = sm + (size_t)(i & 3) * STAGE_F;
        const bool isq = ((S & (NK16T - 1)) * 16) < QIN;

        float4 qa = *(const float4*)(st + mrow * 16 + tg * 4);
        float4 qb = *(const float4*)(st + (mrow + 8) * 16 + tg * 4);
        if (isq) {
            const float4 na = *(const float4*)(st + N_OFF + mrow * 16 + tg * 4);
            const float4 nb = *(const float4*)(st + N_OFF + (mrow + 8) * 16 + tg * 4);
            float w[8]  = {qa.x, qa.y, qa.z, qa.w, qb.x, qb.y, qb.z, qb.w};
            const float nn[8] = {na.x, na.y, na.z, na.w, nb.x, nb.y, nb.z, nb.w};
            #pragma unroll
            for (int e = 0; e < 8; ++e) {
                const float a  = (e < 4) ? a0v : a1v;
                const float dh = (e < 4) ? dh0 : dh1;
                float v = w[e];
                w[e] = (v >= a) ? a : ((v <= -a) ? -a : fmaf(nn[e], dh, v));
            }
            qa = make_float4(w[0], w[1], w[2], w[3]);
            qb = make_float4(w[4], w[5], w[6], w[7]);
        }

        uint32_t ah[4], al[4];
        split2(qa.x, qa.y, ah[0], al[0]);   // (mrow,   b0-slot)
        split2(qa.z, qa.w, ah[2], al[2]);   // (mrow,   b1-slot)
        split2(qb.x, qb.y, ah[1], al[1]);   // (mrow+8, b0-slot)
        split2(qb.z, qb.w, ah[3], al[3]);   // (mrow+8, b1-slot)

        const uint4* bb = (const uint4*)(st + B_OFF);
        #pragma unroll
        for (int n = 0; n < 8; ++n) {
            const uint4 bv = bb[n * 32 + lane];
            mma_bf16(acc[n], ah[0], ah[1], ah[2], ah[3], bv.x, bv.y);
            mma_bf16(acc[n], ah[0], ah[1], ah[2], ah[3], bv.z, bv.w);
            mma_bf16(acc[n], al[0], al[1], al[2], al[3], bv.x, bv.y);
        }
    }

    FLUSH(cur_tile);

    #undef ISSUE
    #undef FLUSH
}

// ---------------------------------------------------------------------------
extern "C" void kernel_launch(void* const* d_in, const int* in_sizes, int n_in,
                              void* d_out, int out_size) {
    const float* input  = (const float*)d_in[0];
    const float* q_w    = (const float*)d_in[1];
    const float* fp_w   = (const float*)d_in[2];
    const float* alpha  = (const float*)d_in[3];
    const float* bias   = (const float*)d_in[4];
    const float* noise  = (const float*)d_in[5];
    const int*   inv    = (const int*)d_in[6];
    float* out = (float*)d_out;
    (void)in_sizes; (void)n_in; (void)out_size;

    static int nsm = 0;
    if (!nsm) {
        cudaDeviceGetAttribute(&nsm, cudaDevAttrMultiProcessorCount, 0);
        if (nsm <= 0) nsm = 148;
        cudaFuncSetAttribute(linear_kernel,
                             cudaFuncAttributeMaxDynamicSharedMemorySize,
                             SMEM_BYTES);
    }

    fwd_kernel<<<IN_F / 256, 256>>>(inv);
    init_out_kernel<<<TOKENS * OUT_F / 4 / 256, 256>>>(bias, out);
    prep_b_kernel<<<IN_F / 64, 256>>>(input);
    linear_kernel<<<2 * nsm, 256, SMEM_BYTES>>>(q_w, fp_w, alpha, noise, out);
}

// round 11
// speedup vs baseline: 4.1193x; 1.0392x over previous
#include <cuda_runtime.h>
#include <cuda_bf16.h>
#include <cstdint>

#define TOKENS   64
#define IN_F     8192
#define OUT_F    8192
#define QIN      7936
#define OUTL     256

#define MT       128                 // out-features per tile
#define TILES    (OUT_F / MT)        // 64
#define NK16T    (IN_F / 16)         // 512 k16 steps per tile
#define TOTAL    (TILES * NK16T)     // 32768 work units

#define STAGES   4
#define A_WARP_F   512               // per-warp stage: 256 q + 256 noise floats (2KB)
#define A_STAGE_F  (8 * A_WARP_F)    // 16KB
#define A_TOTAL_F  (STAGES * A_STAGE_F)          // 64KB
#define B_BYTES    (2 * 4 * 256 * 16)            // 2 bufs x 4 k16 x 256 uint4 = 32KB
#define SMEM_BYTES (A_TOTAL_F * 4 + B_BYTES)     // 98304

// device scratch (no allocations allowed)
__device__ int   g_fwd[IN_F];                 // forward column permutation
__device__ uint4 g_bf[NK16T * 8 * 32];        // B frags [k16][n][lane] {b0h,b1h,b0l,b1l}

// ---------------------------------------------------------------------------
// helpers
// ---------------------------------------------------------------------------
__device__ __forceinline__ uint32_t pack_bf16x2(float hi_elem, float lo_elem) {
    uint32_t d;
    asm("cvt.rn.bf16x2.f32 %0, %1, %2;" : "=r"(d) : "f"(hi_elem), "f"(lo_elem));
    return d;
}
// split (v0 -> low half, v1 -> high half) into bf16 hi and residual lo packs
__device__ __forceinline__ void split2(float v0, float v1,
                                       uint32_t& h, uint32_t& l) {
    h = pack_bf16x2(v1, v0);
    float h0 = __uint_as_float(h << 16);
    float h1 = __uint_as_float(h & 0xFFFF0000u);
    l = pack_bf16x2(v1 - h1, v0 - h0);
}
__device__ __forceinline__ void mma_bf16(float* c,
                                         uint32_t a0, uint32_t a1,
                                         uint32_t a2, uint32_t a3,
                                         uint32_t b0, uint32_t b1) {
    asm volatile(
        "mma.sync.aligned.m16n8k16.row.col.f32.bf16.bf16.f32 "
        "{%0,%1,%2,%3}, {%4,%5,%6,%7}, {%8,%9}, {%0,%1,%2,%3};"
        : "+f"(c[0]), "+f"(c[1]), "+f"(c[2]), "+f"(c[3])
        : "r"(a0), "r"(a1), "r"(a2), "r"(a3), "r"(b0), "r"(b1));
}
__device__ __forceinline__ void cp16(uint32_t dst, const void* src) {
    asm volatile("cp.async.cg.shared.global [%0], [%1], 16;"
                 :: "r"(dst), "l"(src));
}
__device__ __forceinline__ void cp_commit() {
    asm volatile("cp.async.commit_group;" ::: "memory");
}
__device__ __forceinline__ void cp_wait2() {
    asm volatile("cp.async.wait_group 2;" ::: "memory");
}
__device__ __forceinline__ uint32_t smem_u32(const void* p) {
    uint32_t a;
    asm("{ .reg .u64 t; cvta.to.shared.u64 t, %1; cvt.u32.u64 %0, t; }"
        : "=r"(a) : "l"(p));
    return a;
}

// ---------------------------------------------------------------------------
// Kernel 1: forward permutation  g_fwd[inv[j]] = j
// ---------------------------------------------------------------------------
__global__ void fwd_kernel(const int* __restrict__ inv) {
    int j = blockIdx.x * blockDim.x + threadIdx.x;
    if (j < IN_F) g_fwd[inv[j]] = j;
}

// ---------------------------------------------------------------------------
// Kernel 2: init output with bias (accumulation target for RED.ADD)
// ---------------------------------------------------------------------------
__global__ void __launch_bounds__(256)
init_out_kernel(const float* __restrict__ bias, float* __restrict__ out) {
    int i = blockIdx.x * blockDim.x + threadIdx.x;      // float4 index
    int idx = i * 4;
    int o = idx & (OUT_F - 1);
    *(float4*)(out + idx) = *(const float4*)(bias + o);
}

// ---------------------------------------------------------------------------
// Kernel 3: gather permuted input + pack bf16 hi/lo MMA B-fragments.
// k-PERMUTED: physical k 4tg+{0,1} -> frag slots 2tg,2tg+1 (b0),
// physical 4tg+{2,3} -> 2tg+8,2tg+9 (b1). A uses the same mapping.
// ---------------------------------------------------------------------------
__global__ void __launch_bounds__(256)
prep_b_kernel(const float* __restrict__ inp) {
    __shared__ float tile[64][68];
    __shared__ int   jcol[64];
    const int tid = threadIdx.x;
    const int kb  = blockIdx.x * 64;

    if (tid < 64) jcol[tid] = g_fwd[kb + tid];
    __syncthreads();
    {
        const int k = tid >> 2, tq = tid & 3;
        const int j = jcol[k];
        #pragma unroll
        for (int i = 0; i < 16; ++i) {
            int t = tq * 16 + i;
            tile[k][t] = inp[(size_t)t * IN_F + j];
        }
    }
    __syncthreads();

    const int lane = tid & 31, n = tid >> 5;
    const int g = lane >> 2, tg = lane & 3;
    const int t = n * 8 + g;
    #pragma unroll
    for (int k16l = 0; k16l < 4; ++k16l) {
        const int kl = k16l * 16 + tg * 4;
        uint32_t b0h, b0l, b1h, b1l;
        split2(tile[kl][t],     tile[kl + 1][t], b0h, b0l);
        split2(tile[kl + 2][t], tile[kl + 3][t], b1h, b1l);
        g_bf[(size_t)(blockIdx.x * 4 + k16l) * 256 + n * 32 + lane] =
            make_uint4(b0h, b1h, b0l, b1l);
    }
}

// ---------------------------------------------------------------------------
// Kernel 4: persistent fused transform + HMMA GEMM.
// A: per-warp 4-stage cp.async pipeline, gated only by per-warp wait+syncwarp.
// B: register-prefetched, STS'd per 4-step group, one __syncthreads per group.
// ---------------------------------------------------------------------------
__global__ void __launch_bounds__(256, 2)
linear_kernel(const float* __restrict__ q_w, const float* __restrict__ fp_w,
              const float* __restrict__ alpha, const float* __restrict__ noise,
              float* __restrict__ out) {
    extern __shared__ char smraw[];
    float* smA = (float*)smraw;
    uint4* smB = (uint4*)(smraw + A_TOTAL_F * 4);
    const uint32_t sbA = smem_u32(smA);

    const int tid  = threadIdx.x;
    const int wid  = tid >> 5;
    const int lane = tid & 31;
    const int g    = lane >> 2;
    const int tg   = lane & 3;
    const int mrow = wid * 16 + g;           // rows mrow, mrow+8 within tile
    const int ar   = lane >> 1;              // A staging: row 0..15 of own warp
    const int ahh  = lane & 1;               // A staging: 32B half

    const int s_begin = (int)(((long long)TOTAL * blockIdx.x) / gridDim.x);
    const int s_end   = (int)(((long long)TOTAL * (blockIdx.x + 1)) / gridDim.x);
    const int i_end   = s_end - s_begin;

    // ---- A stage issue: per-warp, one commit group per step ----
    #define ISSUE_A(S_)                                                        \
    {                                                                          \
        const int Sc_ = ((S_) < TOTAL) ? (S_) : (TOTAL - 1);                   \
        const int ii_ = (S_) - s_begin;                                        \
        const uint32_t d_ = sbA + (uint32_t)(((ii_ & 3) * A_STAGE_F +          \
                            wid * A_WARP_F + ar * 16 + ahh * 8) * 4);          \
        const int kb_  = (Sc_ & (NK16T - 1)) * 16;                             \
        const int row_ = (Sc_ >> 9) * MT + wid * 16 + ar;                      \
        if (kb_ < QIN) {                                                       \
            const float* q_ = q_w   + (size_t)row_ * QIN + kb_ + ahh * 8;      \
            const float* n_ = noise + (size_t)row_ * QIN + kb_ + ahh * 8;      \
            cp16(d_, q_);       cp16(d_ + 16, q_ + 4);                         \
            cp16(d_ + 1024, n_); cp16(d_ + 1040, n_ + 4);                      \
        } else {                                                               \
            const float* f_ = fp_w + (size_t)row_ * OUTL + (kb_ - QIN) + ahh * 8;\
            cp16(d_, f_);       cp16(d_ + 16, f_ + 4);                         \
        }                                                                      \
        cp_commit();                                                           \
    }

    // ---- B group prefetch / store ----
    uint4 br[4];
    #define LDG_B(j_)                                                          \
    {                                                                          \
        _Pragma("unroll")                                                      \
        for (int u = 0; u < 4; ++u) {                                          \
            int S_ = s_begin + 4 * (j_) + u;                                   \
            if (S_ >= TOTAL) S_ = TOTAL - 1;                                   \
            br[u] = g_bf[(size_t)(S_ & (NK16T - 1)) * 256 + tid];              \
        }                                                                      \
    }
    #define STS_B(buf_)                                                        \
    {                                                                          \
        _Pragma("unroll")                                                      \
        for (int u = 0; u < 4; ++u)                                            \
            smB[(buf_) * 1024 + u * 256 + tid] = br[u];                        \
    }

    float acc[8][4];
    #pragma unroll
    for (int n = 0; n < 8; ++n)
        #pragma unroll
        for (int j = 0; j < 4; ++j) acc[n][j] = 0.0f;

    #define FLUSH(tile_)                                                       \
    {                                                                          \
        const int Rf = (tile_) * MT + mrow;                                    \
        _Pragma("unroll")                                                      \
        for (int n = 0; n < 8; ++n) {                                          \
            const int t = n * 8 + tg * 2;                                      \
            atomicAdd(out + (size_t)t * OUT_F + Rf,           acc[n][0]);      \
            atomicAdd(out + (size_t)(t + 1) * OUT_F + Rf,     acc[n][1]);      \
            atomicAdd(out + (size_t)t * OUT_F + Rf + 8,       acc[n][2]);      \
            atomicAdd(out + (size_t)(t + 1) * OUT_F + Rf + 8, acc[n][3]);      \
        }                                                                      \
    }

    // ---- prologues ----
    ISSUE_A(s_begin);
    ISSUE_A(s_begin + 1);
    ISSUE_A(s_begin + 2);
    LDG_B(0); STS_B(0); LDG_B(1);
    __syncthreads();                         // buf0 visible

    int cur_tile = s_begin >> 9;
    float a0v = alpha[cur_tile * MT + mrow];
    float a1v = alpha[cur_tile * MT + mrow + 8];
    float dh0 = a0v * (0.5f / 7.0f);
    float dh1 = a1v * (0.5f / 7.0f);

    const int G = (i_end + 3) >> 2;
    for (int jg = 0; jg < G; ++jg) {
        if (jg + 1 < G) STS_B((jg + 1) & 1);  // buf consumed in group jg-1: safe
        if (jg + 2 < G) LDG_B(jg + 2);        // refill regs for next group

        #pragma unroll
        for (int u = 0; u < 4; ++u) {
            const int i = 4 * jg + u;
            if (i < i_end) {
                const int S = s_begin + i;
                const int tile = S >> 9;
                if (tile != cur_tile) {
                    FLUSH(cur_tile);
                    #pragma unroll
                    for (int n = 0; n < 8; ++n)
                        #pragma unroll
                        for (int j = 0; j < 4; ++j) acc[n][j] = 0.0f;
                    a0v = alpha[tile * MT + mrow];
                    a1v = alpha[tile * MT + mrow + 8];
                    dh0 = a0v * (0.5f / 7.0f);
                    dh1 = a1v * (0.5f / 7.0f);
                    cur_tile = tile;
                }

                cp_wait2();                   // own stage i landed (3 groups out)
                __syncwarp();
                if (i + 3 < i_end) { ISSUE_A(S + 3); } else { cp_commit(); }

                // ---- consume stage i (per-warp region) ----
                const float* st = smA + (size_t)(i & 3) * A_STAGE_F + wid * A_WARP_F;
                const bool isq = ((S & (NK16T - 1)) * 16) < QIN;

                float4 qa = *(const float4*)(st + g * 16 + tg * 4);
                float4 qb = *(const float4*)(st + (g + 8) * 16 + tg * 4);
                if (isq) {
                    const float4 na = *(const float4*)(st + 256 + g * 16 + tg * 4);
                    const float4 nb = *(const float4*)(st + 256 + (g + 8) * 16 + tg * 4);
                    float w[8] = {qa.x, qa.y, qa.z, qa.w, qb.x, qb.y, qb.z, qb.w};
                    const float nn[8] = {na.x, na.y, na.z, na.w,
                                         nb.x, nb.y, nb.z, nb.w};
                    #pragma unroll
                    for (int e = 0; e < 8; ++e) {
                        const float a  = (e < 4) ? a0v : a1v;
                        const float dh = (e < 4) ? dh0 : dh1;
                        float v = w[e];
                        w[e] = (v >= a) ? a : ((v <= -a) ? -a : fmaf(nn[e], dh, v));
                    }
                    qa = make_float4(w[0], w[1], w[2], w[3]);
                    qb = make_float4(w[4], w[5], w[6], w[7]);
                }

                uint32_t ah[4], al[4];
                split2(qa.x, qa.y, ah[0], al[0]);
                split2(qa.z, qa.w, ah[2], al[2]);
                split2(qb.x, qb.y, ah[1], al[1]);
                split2(qb.z, qb.w, ah[3], al[3]);

                const uint4* bb = smB + ((size_t)(jg & 1)) * 1024 + u * 256;
                #pragma unroll
                for (int n = 0; n < 8; ++n) {
                    const uint4 bv = bb[n * 32 + lane];
                    mma_bf16(acc[n], ah[0], ah[1], ah[2], ah[3], bv.x, bv.y);
                    mma_bf16(acc[n], ah[0], ah[1], ah[2], ah[3], bv.z, bv.w);
                    mma_bf16(acc[n], al[0], al[1], al[2], al[3], bv.x, bv.y);
                }
            }
        }
        __syncthreads();                      // group done; next buf visible
    }

    FLUSH(cur_tile);

    #undef ISSUE_A
    #undef LDG_B
    #undef STS_B
    #undef FLUSH
}

// ---------------------------------------------------------------------------
extern "C" void kernel_launch(void* const* d_in, const int* in_sizes, int n_in,
                              void* d_out, int out_size) {
    const float* input  = (const float*)d_in[0];
    const float* q_w    = (const float*)d_in[1];
    const float* fp_w   = (const float*)d_in[2];
    const float* alpha  = (const float*)d_in[3];
    const float* bias   = (const float*)d_in[4];
    const float* noise  = (const float*)d_in[5];
    const int*   inv    = (const int*)d_in[6];
    float* out = (float*)d_out;
    (void)in_sizes; (void)n_in; (void)out_size;

    static int nsm = 0;
    if (!nsm) {
        cudaDeviceGetAttribute(&nsm, cudaDevAttrMultiProcessorCount, 0);
        if (nsm <= 0) nsm = 148;
        cudaFuncSetAttribute(linear_kernel,
                             cudaFuncAttributeMaxDynamicSharedMemorySize,
                             SMEM_BYTES);
    }

    fwd_kernel<<<IN_F / 256, 256>>>(inv);
    init_out_kernel<<<TOKENS * OUT_F / 4 / 256, 256>>>(bias, out);
    prep_b_kernel<<<IN_F / 64, 256>>>(input);
    linear_kernel<<<2 * nsm, 256, SMEM_BYTES>>>(q_w, fp_w, alpha, noise, out);
}